// round 5
// baseline (speedup 1.0000x reference)
#include <cuda_runtime.h>
#include <cuda_bf16.h>
#include <math.h>
#include <stdint.h>

// VectorQuantizer: bf16 split-precision mma.sync screen + exact fp32 rescore.
// N=131072 rows (dim 64) vs K=512 codes. Out (fp32):
//   [0, 8388608) quantized_st; [8388608, 8519680) codes;
//   then commitment*0.25, codebook_loss, perplexity.
#define K_CODES 512
#define DIMV    64
#define NROWS   131072
#define TPB     256
#define NBLK    148
#define TILE_R  128
#define NTILES  (NROWS / TILE_R)   // 1024
#define TH      2.5e-4f
#define BSTRIDE 144                // bytes per padded bf16 row (64 data + 8 pad)

// smem byte offsets
#define OFF_BHI  0
#define OFF_BLO  (OFF_BHI + K_CODES * BSTRIDE)        // 73728
#define OFF_AHI  (OFF_BLO + K_CODES * BSTRIDE)        // 147456
#define OFF_ALO  (OFF_AHI + TILE_R * BSTRIDE)         // 165888
#define OFF_C2   (OFF_ALO + TILE_R * BSTRIDE)         // 184320
#define OFF_HIST (OFF_C2 + 2048)
#define OFF_CAND (OFF_HIST + 2048)                    // int2[128]
#define OFF_BEST (OFF_CAND + 1024)                    // int[128]
#define OFF_SRED (OFF_BEST + 512)                     // float[256]
#define SMEM_BYTES (OFF_SRED + 1024)

typedef unsigned long long u64;
typedef unsigned int u32;

__device__ double g_sqsum;
__device__ int g_counts[K_CODES];

__global__ void vq_init_kernel() {
    int t = blockIdx.x * blockDim.x + threadIdx.x;
    if (t == 0) g_sqsum = 0.0;
    if (t < K_CODES) g_counts[t] = 0;
}

__device__ __forceinline__ void mma_bf16(float* d, const u32* a, u32 b0, u32 b1) {
    asm volatile(
        "mma.sync.aligned.m16n8k16.row.col.f32.bf16.bf16.f32 "
        "{%0,%1,%2,%3},{%4,%5,%6,%7},{%8,%9},{%0,%1,%2,%3};"
        : "+f"(d[0]), "+f"(d[1]), "+f"(d[2]), "+f"(d[3])
        : "r"(a[0]), "r"(a[1]), "r"(a[2]), "r"(a[3]), "r"(b0), "r"(b1));
}

// order-preserving float->u32 (ascending), then pack with k (lowest-k on ties).
__device__ __forceinline__ u32 f2o(float s) {
    int i = __float_as_int(s);
    return (i >= 0) ? ((u32)i ^ 0x80000000u) : ~(u32)i;
}
__device__ __forceinline__ float o2f(u32 u) {
    return __int_as_float((u & 0x80000000u) ? (int)(u ^ 0x80000000u) : (int)~u);
}
__device__ __forceinline__ void ins3(u64& a, u64& b, u64& c, u64 p) {
    if (p < c) {
        if (p < b) {
            if (p < a) { c = b; b = a; a = p; }
            else       { c = b; b = p; }
        } else c = p;
    }
}

// Exact reference-order score: sequential fma chain, round((x2-2m)+c2).
__device__ __forceinline__ float exact_score(const float* __restrict__ cb,
                                             int k, float c2,
                                             const float* xr, float x2) {
    const float* c = cb + k * DIMV;
    float m = 0.f;
    #pragma unroll
    for (int d = 0; d < DIMV; ++d) m = __fmaf_rn(xr[d], __ldg(c + d), m);
    return __fadd_rn(__fadd_rn(x2, -2.f * m), c2);
}

__device__ __noinline__ int exact_scan_all(const float* __restrict__ cb,
                                           const float* __restrict__ sc2,
                                           const float* xr, float x2) {
    float best = 3.4e38f; int bk = 0;
    for (int k = 0; k < K_CODES; ++k) {
        float s = exact_score(cb, k, sc2[k], xr, x2);
        if (s < best) { best = s; bk = k; }
    }
    return bk;
}

__device__ __forceinline__ void cvt_store(char* dst, float4 v) {
    // pack 4 fp32 -> hi bf16x2 pair is done by caller; helper unused
}

__global__ __launch_bounds__(TPB, 1)
void vq_main_kernel(const float* __restrict__ latents,
                    const float* __restrict__ codebook,
                    float* __restrict__ out) {
    extern __shared__ char sm[];
    float* sc2  = (float*)(sm + OFF_C2);
    int*  shist = (int*)(sm + OFF_HIST);
    int2* scand = (int2*)(sm + OFF_CAND);
    int*  sbest = (int*)(sm + OFF_BEST);
    float* sred = (float*)(sm + OFF_SRED);

    const int tid = threadIdx.x;
    const int wid = tid >> 5, lane = tid & 31;
    const int lrow = lane >> 2, lcol = lane & 3;
    const int rowbase = wid * 16;

    // ---- prologue: codebook hi/lo bf16 (padded rows) + c2 + hist ----
    for (int g = tid; g < K_CODES * 16; g += TPB) {
        int r = g >> 4, i = g & 15;
        float4 v = ((const float4*)codebook)[g];
        __nv_bfloat162 h01 = __floats2bfloat162_rn(v.x, v.y);
        __nv_bfloat162 h23 = __floats2bfloat162_rn(v.z, v.w);
        float lx = v.x - __bfloat162float(h01.x), ly = v.y - __bfloat162float(h01.y);
        float lz = v.z - __bfloat162float(h23.x), lw = v.w - __bfloat162float(h23.y);
        __nv_bfloat162 l01 = __floats2bfloat162_rn(lx, ly);
        __nv_bfloat162 l23 = __floats2bfloat162_rn(lz, lw);
        int off = r * BSTRIDE + i * 8;
        *(uint2*)(sm + OFF_BHI + off) = make_uint2(*(u32*)&h01, *(u32*)&h23);
        *(uint2*)(sm + OFF_BLO + off) = make_uint2(*(u32*)&l01, *(u32*)&l23);
    }
    for (int k = tid; k < K_CODES; k += TPB) {
        const float* c = codebook + k * DIMV;
        float s = 0.f;
        #pragma unroll
        for (int d = 0; d < DIMV; ++d) s = __fadd_rn(s, __fmul_rn(c[d], c[d]));
        sc2[k] = s;
    }
    for (int k = tid; k < K_CODES; k += TPB) shist[k] = 0;
    __syncthreads();

    float sqAcc = 0.f;

    for (int tile = blockIdx.x; tile < NTILES; tile += NBLK) {
        // ---- A tile: fp32 -> bf16 hi/lo into smem ----
        const float4* src = (const float4*)latents + (size_t)tile * (TILE_R * 16);
        for (int f = tid; f < TILE_R * 16; f += TPB) {
            int r = f >> 4, i = f & 15;
            float4 v = src[f];
            __nv_bfloat162 h01 = __floats2bfloat162_rn(v.x, v.y);
            __nv_bfloat162 h23 = __floats2bfloat162_rn(v.z, v.w);
            float lx = v.x - __bfloat162float(h01.x), ly = v.y - __bfloat162float(h01.y);
            float lz = v.z - __bfloat162float(h23.x), lw = v.w - __bfloat162float(h23.y);
            __nv_bfloat162 l01 = __floats2bfloat162_rn(lx, ly);
            __nv_bfloat162 l23 = __floats2bfloat162_rn(lz, lw);
            int off = r * BSTRIDE + i * 8;
            *(uint2*)(sm + OFF_AHI + off) = make_uint2(*(u32*)&h01, *(u32*)&h23);
            *(uint2*)(sm + OFF_ALO + off) = make_uint2(*(u32*)&l01, *(u32*)&l23);
        }
        __syncthreads();

        // ---- load A fragments (16 rows per warp, K=64 -> 4 kfrags) ----
        u32 ahi[16], alo[16];
        {
            int b0 = (rowbase + lrow) * BSTRIDE + lcol * 4;
            #pragma unroll
            for (int kf = 0; kf < 4; ++kf) {
                int o = b0 + kf * 32;
                ahi[kf*4+0] = *(u32*)(sm + OFF_AHI + o);
                ahi[kf*4+1] = *(u32*)(sm + OFF_AHI + o + 8 * BSTRIDE);
                ahi[kf*4+2] = *(u32*)(sm + OFF_AHI + o + 16);
                ahi[kf*4+3] = *(u32*)(sm + OFF_AHI + o + 8 * BSTRIDE + 16);
                alo[kf*4+0] = *(u32*)(sm + OFF_ALO + o);
                alo[kf*4+1] = *(u32*)(sm + OFF_ALO + o + 8 * BSTRIDE);
                alo[kf*4+2] = *(u32*)(sm + OFF_ALO + o + 16);
                alo[kf*4+3] = *(u32*)(sm + OFF_ALO + o + 8 * BSTRIDE + 16);
            }
        }

        // ---- tracking state: top-3 packed per row (2 rows/thread) ----
        u64 t0[2], t1[2], t2[2];
        #pragma unroll
        for (int s = 0; s < 2; ++s) { t0[s] = ~0ull; t1[s] = ~0ull; t2[s] = ~0ull; }

        // ---- screen: 16 chunks x 32 codes ----
        const int bbase = lrow * BSTRIDE + lcol * 4;
        for (int ch = 0; ch < 16; ++ch) {
            float P[16], Q[16], R[16];
            #pragma unroll
            for (int j = 0; j < 16; ++j) { P[j] = 0.f; Q[j] = 0.f; R[j] = 0.f; }
            #pragma unroll
            for (int kf = 0; kf < 4; ++kf) {
                #pragma unroll
                for (int nf = 0; nf < 4; ++nf) {
                    int bo = (ch * 32 + nf * 8) * BSTRIDE + kf * 32 + bbase;
                    u32 bh0 = *(u32*)(sm + OFF_BHI + bo);
                    u32 bh1 = *(u32*)(sm + OFF_BHI + bo + 16);
                    u32 bl0 = *(u32*)(sm + OFF_BLO + bo);
                    u32 bl1 = *(u32*)(sm + OFF_BLO + bo + 16);
                    mma_bf16(P + nf * 4, ahi + kf * 4, bh0, bh1);
                    mma_bf16(Q + nf * 4, alo + kf * 4, bh0, bh1);
                    mma_bf16(R + nf * 4, ahi + kf * 4, bl0, bl1);
                }
            }
            // convert to scores and track
            #pragma unroll
            for (int nf = 0; nf < 4; ++nf) {
                int kc = ch * 32 + nf * 8 + lcol * 2;
                float2 c2v = *(float2*)(sm + OFF_C2 + kc * 4);
                float d0 = P[nf*4+0] + Q[nf*4+0] + R[nf*4+0];
                float d1 = P[nf*4+1] + Q[nf*4+1] + R[nf*4+1];
                float d2r = P[nf*4+2] + Q[nf*4+2] + R[nf*4+2];
                float d3 = P[nf*4+3] + Q[nf*4+3] + R[nf*4+3];
                float s00 = __fmaf_rn(-2.f, d0, c2v.x);
                float s01 = __fmaf_rn(-2.f, d1, c2v.y);
                float s10 = __fmaf_rn(-2.f, d2r, c2v.x);
                float s11 = __fmaf_rn(-2.f, d3, c2v.y);
                ins3(t0[0], t1[0], t2[0], ((u64)f2o(s00) << 32) | (u32)kc);
                ins3(t0[0], t1[0], t2[0], ((u64)f2o(s01) << 32) | (u32)(kc + 1));
                ins3(t0[1], t1[1], t2[1], ((u64)f2o(s10) << 32) | (u32)kc);
                ins3(t0[1], t1[1], t2[1], ((u64)f2o(s11) << 32) | (u32)(kc + 1));
            }
        }

        // ---- cross-lane merge over the 4 lanes sharing each row ----
        #pragma unroll
        for (int m = 1; m <= 2; m <<= 1) {
            #pragma unroll
            for (int s = 0; s < 2; ++s) {
                u64 o0 = __shfl_xor_sync(0xffffffffu, t0[s], m);
                u64 o1 = __shfl_xor_sync(0xffffffffu, t1[s], m);
                u64 o2 = __shfl_xor_sync(0xffffffffu, t2[s], m);
                ins3(t0[s], t1[s], t2[s], o0);
                ins3(t0[s], t1[s], t2[s], o1);
                ins3(t0[s], t1[s], t2[s], o2);
            }
        }
        if (lcol == 0) {
            #pragma unroll
            for (int s = 0; s < 2; ++s) {
                int row = rowbase + lrow + s * 8;
                float s0 = o2f((u32)(t0[s] >> 32));
                float s1 = o2f((u32)(t1[s] >> 32));
                float s2v = o2f((u32)(t2[s] >> 32));
                int k0 = (int)(u32)t0[s];
                int cb2;
                if (s2v <= s0 + TH) cb2 = -2;
                else if (s1 <= s0 + TH) cb2 = (int)(u32)t1[s];
                else cb2 = -1;
                scand[row] = make_int2(k0, cb2);
            }
        }
        __syncthreads();

        // ---- resolution: one thread per row ----
        if (tid < TILE_R) {
            int2 c = scand[tid];
            int best;
            if (c.y == -1) {
                best = c.x;
            } else {
                float xr[DIMV];
                const float4* xp = (const float4*)(latents + ((size_t)tile * TILE_R + tid) * DIMV);
                #pragma unroll
                for (int i = 0; i < 16; ++i) ((float4*)xr)[i] = xp[i];
                float x2 = 0.f;
                #pragma unroll
                for (int d = 0; d < DIMV; ++d) x2 = __fadd_rn(x2, __fmul_rn(xr[d], xr[d]));
                if (c.y == -2) {
                    best = exact_scan_all(codebook, sc2, xr, x2);
                } else {
                    float e0 = exact_score(codebook, c.x, sc2[c.x], xr, x2);
                    float e1 = exact_score(codebook, c.y, sc2[c.y], xr, x2);
                    best = c.x;
                    if (e1 < e0 || (e1 == e0 && c.y < c.x)) best = c.y;
                }
            }
            sbest[tid] = best;
            atomicAdd(&shist[best], 1);
            out[(size_t)NROWS * DIMV + (size_t)tile * TILE_R + tid] = (float)best;
        }
        __syncthreads();

        // ---- epilogue: ST output + loss partial ----
        float4* dst = (float4*)out + (size_t)tile * (TILE_R * 16);
        for (int f = tid; f < TILE_R * 16; f += TPB) {
            int r = f >> 4, i = f & 15;
            float4 l = src[f];
            int k = sbest[r];
            float4 q = ((const float4*)codebook)[k * 16 + i];
            float4 o;
            o.x = __fadd_rn(l.x, __fsub_rn(q.x, l.x));
            o.y = __fadd_rn(l.y, __fsub_rn(q.y, l.y));
            o.z = __fadd_rn(l.z, __fsub_rn(q.z, l.z));
            o.w = __fadd_rn(l.w, __fsub_rn(q.w, l.w));
            dst[f] = o;
            float dx = l.x - q.x, dy = l.y - q.y, dz = l.z - q.z, dw = l.w - q.w;
            sqAcc = fmaf(dx, dx, sqAcc);
            sqAcc = fmaf(dy, dy, sqAcc);
            sqAcc = fmaf(dz, dz, sqAcc);
            sqAcc = fmaf(dw, dw, sqAcc);
        }
        __syncthreads();   // cand/sbest/A reuse next tile
    }

    // ---- reductions ----
    sred[tid] = sqAcc;
    __syncthreads();
    for (int s = TPB / 2; s > 0; s >>= 1) {
        if (tid < s) sred[tid] += sred[tid + s];
        __syncthreads();
    }
    if (tid == 0) atomicAdd(&g_sqsum, (double)sred[0]);
    for (int k = tid; k < K_CODES; k += TPB) {
        int c = shist[k];
        if (c) atomicAdd(&g_counts[k], c);
    }
}

__global__ void vq_finalize_kernel(float* __restrict__ out) {
    __shared__ float red[K_CODES];
    int t = threadIdx.x;
    float p = (float)g_counts[t] / (float)NROWS;
    red[t] = -p * logf(p + 1e-10f);
    __syncthreads();
    for (int s = K_CODES / 2; s > 0; s >>= 1) {
        if (t < s) red[t] += red[t + s];
        __syncthreads();
    }
    if (t == 0) {
        float perp = expf(red[0]);
        float msd = (float)(g_sqsum / (double)((size_t)NROWS * DIMV));
        size_t base = (size_t)NROWS * DIMV + NROWS;
        out[base + 0] = msd * 0.25f;
        out[base + 1] = msd;
        out[base + 2] = perp;
    }
}

extern "C" void kernel_launch(void* const* d_in, const int* in_sizes, int n_in,
                              void* d_out, int out_size) {
    (void)in_sizes; (void)n_in; (void)out_size;
    const float* latents  = (const float*)d_in[0];
    const float* codebook = (const float*)d_in[1];
    float* out = (float*)d_out;

    cudaFuncSetAttribute(vq_main_kernel,
                         cudaFuncAttributeMaxDynamicSharedMemorySize, SMEM_BYTES);
    vq_init_kernel<<<2, 256>>>();
    vq_main_kernel<<<NBLK, TPB, SMEM_BYTES>>>(latents, codebook, out);
    vq_finalize_kernel<<<1, K_CODES>>>(out);
}

// round 9
// speedup vs baseline: 2.0671x; 2.0671x over previous
#include <cuda_runtime.h>
#include <math.h>
#include <stdint.h>

// VectorQuantizer: exact-int8 DP4A screen + exact fp32 rescore.
// N=131072 rows (dim 64) vs K=512 codes. Out (fp32):
//   [0, 8388608) quantized_st; [8388608, 8519680) codes;
//   then commitment*0.25, codebook_loss, perplexity.
#define K_CODES 512
#define DIMV    64
#define NROWS   131072
#define TPB     256
#define NBLK    148
#define ROWS_PER_BLK ((NROWS + NBLK - 1) / NBLK)   // 886
#define SC_F    65024.0f                            // 512*127

// fp32 codebook in smem padded to 68 words/row (bank-spread for gathers)
#define CB_STRIDE_W 68
#define OFF_CBF  0                                  // 512*272 = 139264 B
#define OFF_QCB  (512 * CB_STRIDE_W * 4)            // int8x4 words: 512*16*4 = 32768 B
#define OFF_C2   (OFF_QCB + 32768)                  // 2048 B (reference-order c2)
#define OFF_C1   (OFF_C2 + 2048)                    // 2048 B (per-code |q| sums, int)
#define OFF_HIST (OFF_C1 + 2048)                    // 2048 B
#define OFF_SRED (OFF_HIST + 2048)                  // 1024 B
#define OFF_C1MX (OFF_SRED + 1024)                  // 4 B (int-bits float max)
#define SMEM_BYTES (OFF_C1MX + 16)

typedef unsigned long long u64;
typedef unsigned int u32;

__device__ double g_sqsum;
__device__ int g_counts[K_CODES];

// signed int8x4 dot-accumulate (explicit asm: avoids intrinsic overload ambiguity)
__device__ __forceinline__ int dp4a_s(u32 a, u32 b, int c) {
    int r;
    asm("dp4a.s32.s32 %0, %1, %2, %3;" : "=r"(r) : "r"(a), "r"(b), "r"(c));
    return r;
}

__global__ void vq_init_kernel() {
    int t = blockIdx.x * blockDim.x + threadIdx.x;
    if (t == 0) g_sqsum = 0.0;
    if (t < K_CODES) g_counts[t] = 0;
}

// order-preserving float->u32 (ascending; all scores finite)
__device__ __forceinline__ u32 f2o(float s) {
    int i = __float_as_int(s);
    return (i >= 0) ? ((u32)i ^ 0x80000000u) : ~(u32)i;
}
__device__ __forceinline__ float o2f(u32 u) {
    return __int_as_float((u & 0x80000000u) ? (int)(u ^ 0x80000000u) : (int)~u);
}
__device__ __forceinline__ void ins4(u64& a, u64& b, u64& c, u64& d, u64 p) {
    if (p < d) {
        if (p < c) {
            d = c;
            if (p < b) { c = b; if (p < a) { b = a; a = p; } else b = p; }
            else c = p;
        } else d = p;
    }
}

// Exact reference-order score from padded smem codebook:
// sequential fma chain d=0..63, then round(round(x2-2m)+c2).
__device__ __forceinline__ float exact_score_sm(const float* __restrict__ cbf,
                                                int k, float c2,
                                                const float* xr, float x2) {
    const float* c = cbf + k * CB_STRIDE_W;
    float m = 0.f;
    #pragma unroll
    for (int d = 0; d < DIMV; ++d) m = __fmaf_rn(xr[d], c[d], m);
    return __fadd_rn(__fadd_rn(x2, -2.f * m), c2);
}

__device__ __noinline__ int exact_scan_all(const float* __restrict__ cbf,
                                           const float* __restrict__ sc2,
                                           const float* xr, float x2) {
    float best = 3.4e38f; int bk = 0;
    for (int k = 0; k < K_CODES; ++k) {
        float s = exact_score_sm(cbf, k, sc2[k], xr, x2);
        if (s < best) { best = s; bk = k; }
    }
    return bk;
}

__global__ __launch_bounds__(TPB, 1)
void vq_main_kernel(const float* __restrict__ latents,
                    const float* __restrict__ codebook,
                    float* __restrict__ out) {
    extern __shared__ char sm[];
    float* cbf  = (float*)(sm + OFF_CBF);     // padded fp32 codebook
    u32*  qcb   = (u32*)(sm + OFF_QCB);       // int8x4 codebook, 16 words/code
    float* sc2  = (float*)(sm + OFF_C2);
    int*  c1arr = (int*)(sm + OFF_C1);
    int*  shist = (int*)(sm + OFF_HIST);
    float* sred = (float*)(sm + OFF_SRED);
    int*  c1mx  = (int*)(sm + OFF_C1MX);

    const int tid = threadIdx.x;

    // ---- init: fp32 padded codebook + int8 quantized codebook + c1 sums ----
    for (int k = tid; k < K_CODES; k += TPB) c1arr[k] = 0;
    if (tid == 0) *c1mx = 0;
    for (int k = tid; k < K_CODES; k += TPB) shist[k] = 0;
    __syncthreads();
    for (int g = tid; g < K_CODES * 16; g += TPB) {
        int k = g >> 4, i = g & 15;          // i: float4 index (4 dims)
        float4 v = ((const float4*)codebook)[g];
        *(float4*)(cbf + k * CB_STRIDE_W + i * 4) = v;
        int q0 = __float2int_rn(v.x * SC_F);
        int q1 = __float2int_rn(v.y * SC_F);
        int q2 = __float2int_rn(v.z * SC_F);
        int q3 = __float2int_rn(v.w * SC_F);
        qcb[g] = (u32)(q0 & 0xFF) | ((u32)(q1 & 0xFF) << 8) |
                 ((u32)(q2 & 0xFF) << 16) | ((u32)q3 << 24);
        atomicAdd(&c1arr[k], abs(q0) + abs(q1) + abs(q2) + abs(q3));
    }
    __syncthreads();
    // C1max = max_k (sum|qc| + 0.5*64)/Sc  (float bits monotone: values > 0)
    for (int k = tid; k < K_CODES; k += TPB) {
        float c1 = ((float)c1arr[k] + 32.0f) * (1.0f / SC_F);
        atomicMax(c1mx, __float_as_int(c1));
    }
    // reference-order c2
    for (int k = tid; k < K_CODES; k += TPB) {
        const float* c = cbf + k * CB_STRIDE_W;
        float s = 0.f;
        #pragma unroll
        for (int d = 0; d < DIMV; ++d) s = __fadd_rn(s, __fmul_rn(c[d], c[d]));
        sc2[k] = s;
    }
    __syncthreads();
    const float C1max = __int_as_float(*c1mx);

    const int row0 = blockIdx.x * ROWS_PER_BLK;
    const int rowEnd = min(row0 + ROWS_PER_BLK, NROWS);
    float sqAcc = 0.f;

    for (int row = row0 + tid; row < rowEnd; row += TPB) {
        const float* xg = latents + (size_t)row * DIMV;

        // ---- quantize row: per-row scale, pack int8x4, track sums ----
        float x[DIMV];
        const float4* xp4 = (const float4*)xg;
        #pragma unroll
        for (int i = 0; i < 16; ++i) ((float4*)x)[i] = xp4[i];
        float mx = 0.f, sax = 0.f;
        #pragma unroll
        for (int d = 0; d < DIMV; ++d) {
            float a = fabsf(x[d]);
            mx = fmaxf(mx, a);
            sax += a;
        }
        const float Sx = 127.0f / mx;
        const float dX = 0.502f / Sx;
        u32 qx[16];
        #pragma unroll
        for (int i = 0; i < 16; ++i) {
            int q0 = __float2int_rn(x[4*i+0] * Sx);
            int q1 = __float2int_rn(x[4*i+1] * Sx);
            int q2 = __float2int_rn(x[4*i+2] * Sx);
            int q3 = __float2int_rn(x[4*i+3] * Sx);
            qx[i] = (u32)(q0 & 0xFF) | ((u32)(q1 & 0xFF) << 8) |
                    ((u32)(q2 & 0xFF) << 16) | ((u32)q3 << 24);
        }
        // rigorous per-row window
        const float X1b = sax * 1.0001f + 64.0f * dX;
        const float B = 2.0f * (dX * C1max + (0.502f / SC_F) * X1b) + 1e-4f;
        const float m2inv = -2.0f / (Sx * SC_F);

        // ---- screen: exact int dots, track 4 smallest scores ----
        u64 t0 = ~0ull, t1 = ~0ull, t2 = ~0ull, t3 = ~0ull;
        for (int k0 = 0; k0 < K_CODES; k0 += 4) {
            int dot[4];
            #pragma unroll
            for (int j = 0; j < 4; ++j) {
                const uint4* q = (const uint4*)(qcb + (k0 + j) * 16);
                uint4 a = q[0], b = q[1], c = q[2], d = q[3];
                int s = 0;
                s = dp4a_s(a.x, qx[0],  s); s = dp4a_s(a.y, qx[1],  s);
                s = dp4a_s(a.z, qx[2],  s); s = dp4a_s(a.w, qx[3],  s);
                s = dp4a_s(b.x, qx[4],  s); s = dp4a_s(b.y, qx[5],  s);
                s = dp4a_s(b.z, qx[6],  s); s = dp4a_s(b.w, qx[7],  s);
                s = dp4a_s(c.x, qx[8],  s); s = dp4a_s(c.y, qx[9],  s);
                s = dp4a_s(c.z, qx[10], s); s = dp4a_s(c.w, qx[11], s);
                s = dp4a_s(d.x, qx[12], s); s = dp4a_s(d.y, qx[13], s);
                s = dp4a_s(d.z, qx[14], s); s = dp4a_s(d.w, qx[15], s);
                dot[j] = s;
            }
            #pragma unroll
            for (int j = 0; j < 4; ++j) {
                float s = __fmaf_rn((float)dot[j], m2inv, sc2[k0 + j]);
                u64 p = ((u64)f2o(s) << 32) | (u32)(k0 + j);
                ins4(t0, t1, t2, t3, p);
            }
        }

        // ---- resolve ----
        const float smin = o2f((u32)(t0 >> 32));
        const float lim = smin + B;
        int best = (int)(u32)t0;
        if (o2f((u32)(t1 >> 32)) <= lim) {
            // exact rescore needed
            float x2 = 0.f;
            #pragma unroll
            for (int d = 0; d < DIMV; ++d) x2 = __fadd_rn(x2, __fmul_rn(x[d], x[d]));
            if (o2f((u32)(t3 >> 32)) <= lim) {
                best = exact_scan_all(cbf, sc2, x, x2);
            } else {
                u64 tt[4] = { t0, t1, t2, t3 };
                float ebest = 3.4e38f; best = K_CODES;
                #pragma unroll
                for (int i = 0; i < 4; ++i) {
                    if (o2f((u32)(tt[i] >> 32)) <= lim) {
                        int k = (int)(u32)tt[i];
                        float e = exact_score_sm(cbf, k, sc2[k], x, x2);
                        if (e < ebest || (e == ebest && k < best)) { ebest = e; best = k; }
                    }
                }
            }
        }

        // ---- epilogue: ST output (reference roundings) + loss + hist ----
        float* qout = out + (size_t)row * DIMV;
        const float* cq = cbf + best * CB_STRIDE_W;
        float rowsq = 0.f;
        #pragma unroll
        for (int i = 0; i < 16; ++i) {
            float4 q = *(const float4*)(cq + i * 4);
            float lx = x[4*i+0], ly = x[4*i+1], lz = x[4*i+2], lw = x[4*i+3];
            float4 o;
            o.x = __fadd_rn(lx, __fsub_rn(q.x, lx));
            o.y = __fadd_rn(ly, __fsub_rn(q.y, ly));
            o.z = __fadd_rn(lz, __fsub_rn(q.z, lz));
            o.w = __fadd_rn(lw, __fsub_rn(q.w, lw));
            ((float4*)qout)[i] = o;
            float dx = lx - q.x, dy = ly - q.y, dz = lz - q.z, dw = lw - q.w;
            rowsq = fmaf(dx, dx, rowsq);
            rowsq = fmaf(dy, dy, rowsq);
            rowsq = fmaf(dz, dz, rowsq);
            rowsq = fmaf(dw, dw, rowsq);
        }
        out[(size_t)NROWS * DIMV + row] = (float)best;
        atomicAdd(&shist[best], 1);
        sqAcc += rowsq;
    }

    // ---- reductions ----
    sred[tid] = sqAcc;
    __syncthreads();
    for (int s = TPB / 2; s > 0; s >>= 1) {
        if (tid < s) sred[tid] += sred[tid + s];
        __syncthreads();
    }
    if (tid == 0) atomicAdd(&g_sqsum, (double)sred[0]);
    for (int k = tid; k < K_CODES; k += TPB) {
        int c = shist[k];
        if (c) atomicAdd(&g_counts[k], c);
    }
}

__global__ void vq_finalize_kernel(float* __restrict__ out) {
    __shared__ float red[K_CODES];
    int t = threadIdx.x;
    float p = (float)g_counts[t] / (float)NROWS;
    red[t] = -p * logf(p + 1e-10f);
    __syncthreads();
    for (int s = K_CODES / 2; s > 0; s >>= 1) {
        if (t < s) red[t] += red[t + s];
        __syncthreads();
    }
    if (t == 0) {
        float perp = expf(red[0]);
        float msd = (float)(g_sqsum / (double)((size_t)NROWS * DIMV));
        size_t base = (size_t)NROWS * DIMV + NROWS;
        out[base + 0] = msd * 0.25f;
        out[base + 1] = msd;
        out[base + 2] = perp;
    }
}

extern "C" void kernel_launch(void* const* d_in, const int* in_sizes, int n_in,
                              void* d_out, int out_size) {
    (void)in_sizes; (void)n_in; (void)out_size;
    const float* latents  = (const float*)d_in[0];
    const float* codebook = (const float*)d_in[1];
    float* out = (float*)d_out;

    cudaFuncSetAttribute(vq_main_kernel,
                         cudaFuncAttributeMaxDynamicSharedMemorySize, SMEM_BYTES);
    vq_init_kernel<<<2, 256>>>();
    vq_main_kernel<<<NBLK, TPB, SMEM_BYTES>>>(latents, codebook, out);
    vq_finalize_kernel<<<1, K_CODES>>>(out);
}

// round 10
// speedup vs baseline: 3.8810x; 1.8775x over previous
#include <cuda_runtime.h>
#include <math.h>

// VectorQuantizer: N=131072 rows of dim 64 vs 512 codes of dim 64.
// Exact bitwise replication of the reference fp32 pipeline (R2-proven):
//   mm  = sequential fma chain d=0..63
//   x2,c2 = sequential sum of round(v*v)
//   d2  = round( round(x2 - 2*mm) + c2 ),  argmin = first-min (strict <)
// Config: persistent 148 blocks x 512 threads -> 4 warps/SMSP (latency
// hiding) AND no wave quantization. FMA-pipe-bound by design.
#define K_CODES 512
#define DIMV 64
#define NROWS 131072
#define TPB 512
#define NBLK 148
#define ROWS_PER_BLK ((NROWS + NBLK - 1) / NBLK)   // 886

__device__ double g_sqsum;
__device__ int g_counts[K_CODES];

__global__ void vq_init_kernel() {
    int t = blockIdx.x * blockDim.x + threadIdx.x;
    if (t == 0) g_sqsum = 0.0;
    if (t < K_CODES) g_counts[t] = 0;
}

__global__ __launch_bounds__(TPB, 1)
void vq_main_kernel(const float* __restrict__ latents,
                    const float* __restrict__ codebook,
                    float* __restrict__ out) {
    extern __shared__ float smem[];
    float* scb   = smem;                        // 512*64 floats (128 KB)
    float* sc2   = smem + K_CODES * DIMV;       // 512
    int*   shist = (int*)(sc2 + K_CODES);       // 512
    float* sred  = (float*)(shist + K_CODES);   // TPB

    const int tid = threadIdx.x;

    // Cooperative codebook load (reused by all rows of this block).
    const float4* cb4 = (const float4*)codebook;
    float4* scb4 = (float4*)scb;
    for (int i = tid; i < K_CODES * DIMV / 4; i += TPB)
        scb4[i] = cb4[i];
    for (int k = tid; k < K_CODES; k += TPB) shist[k] = 0;
    __syncthreads();
    // c2 in reference rounding order (separate mul/add, sequential d).
    for (int k = tid; k < K_CODES; k += TPB) {
        float s = 0.f;
        const float* c = scb + k * DIMV;
        #pragma unroll
        for (int d = 0; d < DIMV; ++d) s = __fadd_rn(s, __fmul_rn(c[d], c[d]));
        sc2[k] = s;
    }
    __syncthreads();

    const int row0 = blockIdx.x * ROWS_PER_BLK;
    const int rowEnd = min(row0 + ROWS_PER_BLK, NROWS);

    float sqAcc = 0.f;   // per-thread loss partial across rows

    for (int row = row0 + tid; row < rowEnd; row += TPB) {
        // Latent row in registers (16 x float4). Never address-taken.
        float4 xv[16];
        const float4* lp = (const float4*)(latents + (size_t)row * DIMV);
        #pragma unroll
        for (int i = 0; i < 16; ++i) xv[i] = lp[i];

        // x2: sequential over d, separate mul/add roundings.
        float x2 = 0.f;
        #pragma unroll
        for (int i = 0; i < 16; ++i) {
            x2 = __fadd_rn(x2, __fmul_rn(xv[i].x, xv[i].x));
            x2 = __fadd_rn(x2, __fmul_rn(xv[i].y, xv[i].y));
            x2 = __fadd_rn(x2, __fmul_rn(xv[i].z, xv[i].z));
            x2 = __fadd_rn(x2, __fmul_rn(xv[i].w, xv[i].w));
        }

        // argmin over reference-rounded scores. 8 codes in flight (ILP);
        // each code's dot is a strict sequential fp32 fma chain d=0..63.
        float best = 3.4e38f;
        int bestk = 0;
        for (int k0 = 0; k0 < K_CODES; k0 += 8) {
            float acc[8];
            #pragma unroll
            for (int j = 0; j < 8; ++j) acc[j] = 0.f;
            #pragma unroll
            for (int dv = 0; dv < 16; ++dv) {
                const float4 xd = xv[dv];
                #pragma unroll
                for (int j = 0; j < 8; ++j) {
                    const float4 cd = ((const float4*)(scb + (k0 + j) * DIMV))[dv];
                    float a = acc[j];
                    a = __fmaf_rn(xd.x, cd.x, a);
                    a = __fmaf_rn(xd.y, cd.y, a);
                    a = __fmaf_rn(xd.z, cd.z, a);
                    a = __fmaf_rn(xd.w, cd.w, a);
                    acc[j] = a;
                }
            }
            #pragma unroll
            for (int j = 0; j < 8; ++j) {
                // (x2 - 2*mm) rounds once (2*mm exact), then +c2 rounds.
                float s = __fadd_rn(__fadd_rn(x2, -2.f * acc[j]), sc2[k0 + j]);
                if (s < best) { best = s; bestk = k0 + j; }  // first-min
            }
        }

        // Epilogue: ST output (reference roundings) + fused loss partial.
        float* qout = out + (size_t)row * DIMV;
        const float4* cq = (const float4*)(scb + bestk * DIMV);
        float rowsq = 0.f;
        #pragma unroll
        for (int i = 0; i < 16; ++i) {
            float4 q = cq[i];
            float4 l = xv[i];
            float4 o;
            o.x = __fadd_rn(l.x, __fsub_rn(q.x, l.x));
            o.y = __fadd_rn(l.y, __fsub_rn(q.y, l.y));
            o.z = __fadd_rn(l.z, __fsub_rn(q.z, l.z));
            o.w = __fadd_rn(l.w, __fsub_rn(q.w, l.w));
            float dx = l.x - q.x, dy = l.y - q.y, dz = l.z - q.z, dw = l.w - q.w;
            rowsq = fmaf(dx, dx, rowsq);
            rowsq = fmaf(dy, dy, rowsq);
            rowsq = fmaf(dz, dz, rowsq);
            rowsq = fmaf(dw, dw, rowsq);
            ((float4*)qout)[i] = o;
        }
        out[(size_t)NROWS * DIMV + row] = (float)bestk;
        atomicAdd(&shist[bestk], 1);
        sqAcc += rowsq;
    }

    // Block reduce loss partial, one double atomic per block.
    sred[tid] = sqAcc;
    __syncthreads();
    for (int s = TPB / 2; s > 0; s >>= 1) {
        if (tid < s) sred[tid] += sred[tid + s];
        __syncthreads();
    }
    if (tid == 0) atomicAdd(&g_sqsum, (double)sred[0]);
    // Flush smem histogram to global.
    for (int k = tid; k < K_CODES; k += TPB) {
        int c = shist[k];
        if (c) atomicAdd(&g_counts[k], c);
    }
}

__global__ void vq_finalize_kernel(float* __restrict__ out) {
    __shared__ float red[K_CODES];
    int t = threadIdx.x;
    float p = (float)g_counts[t] / (float)NROWS;
    red[t] = -p * logf(p + 1e-10f);
    __syncthreads();
    for (int s = K_CODES / 2; s > 0; s >>= 1) {
        if (t < s) red[t] += red[t + s];
        __syncthreads();
    }
    if (t == 0) {
        float perp = expf(red[0]);
        float msd = (float)(g_sqsum / (double)((size_t)NROWS * DIMV));
        size_t base = (size_t)NROWS * DIMV + NROWS;
        out[base + 0] = msd * 0.25f;   // commitment * COMMITMENT_COST
        out[base + 1] = msd;           // codebook loss
        out[base + 2] = perp;          // perplexity
    }
}

extern "C" void kernel_launch(void* const* d_in, const int* in_sizes, int n_in,
                              void* d_out, int out_size) {
    (void)in_sizes; (void)n_in; (void)out_size;
    const float* latents  = (const float*)d_in[0];
    const float* codebook = (const float*)d_in[1];
    float* out = (float*)d_out;

    const int smem_bytes = (K_CODES * DIMV) * 4   // codebook
                         + K_CODES * 4            // c2
                         + K_CODES * 4            // hist
                         + TPB * 4;               // reduce
    cudaFuncSetAttribute(vq_main_kernel,
                         cudaFuncAttributeMaxDynamicSharedMemorySize, smem_bytes);

    vq_init_kernel<<<2, 256>>>();
    vq_main_kernel<<<NBLK, TPB, smem_bytes>>>(latents, codebook, out);
    vq_finalize_kernel<<<1, K_CODES>>>(out);
}